// round 5
// baseline (speedup 1.0000x reference)
#include <cuda_runtime.h>
#include <cstdint>

#define BATCH 2
#define APTS 20000
#define NUMC 512
#define BN 1024
#define NNEI 192
#define GNUM 64

static __device__ float g_px[BATCH*APTS], g_py[BATCH*APTS], g_pz[BATCH*APTS], g_xx[BATCH*APTS];
static __device__ float g_RtC[BN][12];   // Rt rows (9) + center (3)
static __device__ int   g_gmask[BN];
static __device__ float g_gpts[BN*GNUM*3];
static __device__ float g_W2t[512*256];
static __device__ float g_W3t[256*256];
static __device__ float g_W4t[256*128];
static __device__ float g_h2[BN*64*256];   // 64 MB
static __device__ float g_h3[BN*64*256];   // 64 MB

// ---------------- prep kernels ----------------

__global__ void prep_points(const float* __restrict__ pc) {
  int i = blockIdx.x*blockDim.x + threadIdx.x;
  if (i >= BATCH*APTS) return;
  float x = pc[i*6+0], y = pc[i*6+1], z = pc[i*6+2];
  g_px[i]=x; g_py[i]=y; g_pz[i]=z;
  g_xx[i] = __fadd_rn(__fadd_rn(__fmul_rn(x,x),__fmul_rn(y,y)),__fmul_rn(z,z));
}

__global__ void prep_grasp(const float* __restrict__ grasp) {
  int g = blockIdx.x*blockDim.x + threadIdx.x;
  if (g >= BN) return;
  const float* gr = grasp + g*8;
  float s8 = 0.f;
  for (int k=0;k<8;k++) s8 += gr[k];
  g_gmask[g] = (s8 != -8.0f) ? 1 : 0;
  float cx=gr[0], cy=gr[1], cz=gr[2];
  float ay0=gr[3], ay1=gr[4], ay2=gr[5];
  float ang=gr[6];
  float c=cosf(ang), s=sinf(ang);
  float ny = sqrtf(ay0*ay0+ay1*ay1+ay2*ay2);
  ay0 = ay0/(ny+1e-12f); ay1 = ay1/(ny+1e-12f); ay2 = ay2/(ny+1e-12f);
  float ax0=ay1, ax1=-ay0, ax2=0.f;
  float nx = sqrtf(ax0*ax0+ax1*ax1+ax2*ax2);
  ax0 = ax0/(nx+1e-12f); ax1 = ax1/(nx+1e-12f); ax2 = 0.f;
  float az0 = ax1*ay2 - ax2*ay1;
  float az1 = ax2*ay0 - ax0*ay2;
  float az2 = ax0*ay1 - ax1*ay0;
  float nz = sqrtf(az0*az0+az1*az1+az2*az2);
  if (nz == 0.0f) { az0=0.f; az1=0.f; az2=1.f; }
  else { az0/=nz; az1/=nz; az2/=nz; }
  float ap0 = c*ax0 + s*az0;
  float ap1 = c*ax1 + s*az1;
  float ap2 = c*ax2 + s*az2;
  float na = sqrtf(ap0*ap0+ap1*ap1+ap2*ap2);
  ap0 = ap0/(na+1e-12f); ap1 = ap1/(na+1e-12f); ap2 = ap2/(na+1e-12f);
  float mn0 = ap1*ay2 - ap2*ay1;
  float mn1 = ap2*ay0 - ap0*ay2;
  float mn2 = ap0*ay1 - ap1*ay0;
  float* R = g_RtC[g];
  R[0]=ap0; R[1]=ap1; R[2]=ap2;
  R[3]=ay0; R[4]=ay1; R[5]=ay2;
  R[6]=mn0; R[7]=mn1; R[8]=mn2;
  R[9]=cx;  R[10]=cy; R[11]=cz;
}

__global__ void transpose_w(const float* __restrict__ W2, const float* __restrict__ W3,
                            const float* __restrict__ W4) {
  int id = blockIdx.x*blockDim.x + threadIdx.x;
  if (id < 512*256) {
    int k = id >> 8, o = id & 255;
    g_W2t[id] = W2[o*512 + k];
  } else if (id < 512*256 + 256*256) {
    int r = id - 512*256;
    int k = r >> 8, o = r & 255;
    g_W3t[r] = W3[o*256 + k];
  } else if (id < 512*256 + 256*256 + 256*128) {
    int r = id - (512*256 + 256*256);
    int k = r >> 7, o = r & 127;
    g_W4t[r] = W4[o*256 + k];
  }
}

// ---------------- ball query + gripper transform + selection ----------------

__global__ void __launch_bounds__(128) bq_kernel(const float* __restrict__ grasp,
                                                 float* __restrict__ out) {
  __shared__ int s_list[4][NNEI];
  __shared__ int s_app[4], s_tot[4];
  __shared__ int s_nbr[NNEI];
  __shared__ float s_t[NNEI][3];
  __shared__ unsigned char s_in[NNEI];
  __shared__ int s_sel[GNUM];
  __shared__ int s_totvalid, s_ccount;
  __shared__ float s_R[12];

  int g = blockIdx.x;
  int b = g >> 9;
  int tx = threadIdx.x;
  int w = tx >> 5, lane = tx & 31;
  const float* gr = grasp + g*8;
  float cx=gr[0], cy=gr[1], cz=gr[2];
  float cc = __fadd_rn(__fadd_rn(__fmul_rn(cx,cx),__fmul_rn(cy,cy)),__fmul_rn(cz,cz));
  if (tx < 12) s_R[tx] = g_RtC[g][tx];

  const int chunk = APTS/4; // 5000
  int lo = b*APTS + w*chunk, hi = lo + chunk;
  int tot=0, app=0;
  for (int base=lo; base<hi; base+=32) {
    int i = base + lane;
    bool ok=false;
    if (i < hi) {
      float dot = __fadd_rn(__fadd_rn(__fmul_rn(cx,g_px[i]),__fmul_rn(cy,g_py[i])),
                            __fmul_rn(cz,g_pz[i]));
      float d2 = __fsub_rn(__fadd_rn(cc, g_xx[i]), __fmul_rn(2.0f,dot));
      ok = d2 < 0.09f;
    }
    unsigned mb = __ballot_sync(0xffffffffu, ok);
    if (ok) {
      int pos = app + __popc(mb & ((1u<<lane)-1u));
      if (pos < NNEI) s_list[w][pos] = i - b*APTS;
    }
    tot += __popc(mb);
    app = tot < NNEI ? tot : NNEI;
  }
  if (lane==0) { s_app[w]=app; s_tot[w]=tot; }
  __syncthreads();

  if (tx==0) {
    int totv = s_tot[0]+s_tot[1]+s_tot[2]+s_tot[3];
    int run=0;
    for (int ww=0; ww<4 && run<NNEI; ww++) {
      int t = s_app[ww]; if (t > NNEI-run) t = NNEI-run;
      for (int j=0;j<t;j++) s_nbr[run+j] = s_list[ww][j];
      run += t;
    }
    int pad = (run>0) ? s_nbr[0] : 0;
    for (int j=run;j<NNEI;j++) s_nbr[j]=pad;
    s_totvalid = totv;
  }
  __syncthreads();

  for (int p=tx; p<NNEI; p+=blockDim.x) {
    int i = b*APTS + s_nbr[p];
    float vx = g_px[i]-s_R[9], vy = g_py[i]-s_R[10], vz = g_pz[i]-s_R[11];
    float t0 = s_R[0]*vx + s_R[1]*vy + s_R[2]*vz;
    float t1 = s_R[3]*vx + s_R[4]*vy + s_R[5]*vz;
    float t2 = s_R[6]*vx + s_R[7]*vy + s_R[8]*vz;
    s_t[p][0]=t0; s_t[p][1]=t1; s_t[p][2]=t2;
    bool ins = (t0>0.0f)&&(t0<0.3f)&&(t1>-0.15f)&&(t1<0.15f)&&(t2>-0.1f)&&(t2<0.1f);
    s_in[p] = ins ? 1 : 0;
  }
  __syncthreads();

  if (tx < 32) {
    int totI=0, first=-1;
    for (int ch=0; ch<NNEI/32; ch++) {
      int p = ch*32 + lane;
      bool ok = s_in[p]!=0;
      unsigned mm = __ballot_sync(0xffffffffu, ok);
      int app64 = totI<GNUM ? totI : GNUM;
      if (ok) {
        int pos = app64 + __popc(mm & ((1u<<lane)-1u));
        if (pos < GNUM) s_sel[pos] = p;
      }
      if (first<0 && mm) first = ch*32 + __ffs(mm)-1;
      totI += __popc(mm);
    }
    int cc64 = totI<GNUM ? totI : GNUM;
    int pad = (totI>0) ? first : 0;
    for (int j=lane; j<GNUM; j+=32) if (j>=cc64) s_sel[j]=pad;
    if (lane==0) s_ccount = cc64;
  }
  __syncthreads();

  for (int idx=tx; idx<GNUM*3; idx+=blockDim.x) {
    int n = idx/3, d = idx - n*3;
    g_gpts[g*(GNUM*3)+idx] = s_t[s_sel[n]][d];
  }
  if (tx==0) {
    bool mk = (s_totvalid>0) && (s_ccount>0) && (g_gmask[g]!=0);
    out[10240 + g] = mk ? 1.0f : 0.0f;
  }
}

// ---------------- f32x2 helpers ----------------

__device__ __forceinline__ unsigned long long dup2f(float v){
  unsigned long long r; unsigned u = __float_as_uint(v);
  asm("mov.b64 %0, {%1, %1};" : "=l"(r) : "r"(u));
  return r;
}
__device__ __forceinline__ unsigned long long pack2f(float lo, float hi){
  unsigned long long r;
  asm("mov.b64 %0, {%1, %2};" : "=l"(r) : "r"(__float_as_uint(lo)), "r"(__float_as_uint(hi)));
  return r;
}
__device__ __forceinline__ void unpack2f(unsigned long long p, float &lo, float &hi){
  unsigned a, b;
  asm("mov.b64 {%0, %1}, %2;" : "=r"(a), "=r"(b) : "l"(p));
  lo = __uint_as_float(a); hi = __uint_as_float(b);
}
__device__ __forceinline__ void ffma2(unsigned long long &d, unsigned long long a, unsigned long long b){
  asm("fma.rn.f32x2 %0, %1, %2, %0;" : "+l"(d) : "l"(a), "l"(b));
}

// ---------------- layer 1+2 fused: h2 = relu(W2 @ relu(W1 @ pts + b1) + b2) ----------------
// one block per grasp, 256 threads: 8 n-groups x 32 o-groups, O=256 (8 o/thread as 4 f32x2)

__global__ void __launch_bounds__(256) layer12_kernel(
  const float* __restrict__ W1, const float* __restrict__ b1, const float* __restrict__ b2)
{
  __shared__ float s_pts[GNUM*3];
  __shared__ float s_h1[64*32];
  __shared__ float s_w[32*256];
  int tx = threadIdx.x;
  int g = blockIdx.x;
  if (tx < GNUM*3) s_pts[tx] = g_gpts[g*(GNUM*3)+tx];

  int ng = tx >> 5, og = tx & 31;
  int n0 = ng*8, o0 = og*8;
  unsigned long long acc[8][4];
  #pragma unroll
  for (int p=0;p<4;p++) {
    unsigned long long bb = pack2f(b2[o0+2*p], b2[o0+2*p+1]);
    #pragma unroll
    for (int i=0;i<8;i++) acc[i][p] = bb;
  }

  int kk_me = tx & 31;           // this thread's fixed kk for h1 tiles
  int nbase = tx >> 5;           // n = nbase + 8*t
  __syncthreads();

  for (int kt=0; kt<16; kt++) {
    // stage W2t tile [32][256]
    #pragma unroll
    for (int t=0;t<32;t++) s_w[tx + 256*t] = g_W2t[kt*8192 + tx + 256*t];
    // compute h1 tile [64][32]
    int k = kt*32 + kk_me;
    float w0=W1[k*3], w1=W1[k*3+1], w2=W1[k*3+2], bb1=b1[k];
    #pragma unroll
    for (int t=0;t<8;t++) {
      int n = nbase + 8*t;
      float v = fmaf(w2, s_pts[n*3+2], fmaf(w1, s_pts[n*3+1], fmaf(w0, s_pts[n*3+0], bb1)));
      s_h1[n*32 + kk_me] = v>0.f ? v : 0.f;
    }
    __syncthreads();
    #pragma unroll 8
    for (int kk=0; kk<32; kk++) {
      unsigned long long bf[4];
      const float* wr = s_w + kk*256 + o0;
      #pragma unroll
      for (int p=0;p<4;p++) bf[p] = *reinterpret_cast<const unsigned long long*>(wr + 2*p);
      #pragma unroll
      for (int i=0;i<8;i++) {
        unsigned long long aa = dup2f(s_h1[(n0+i)*32 + kk]);
        #pragma unroll
        for (int p=0;p<4;p++) ffma2(acc[i][p], aa, bf[p]);
      }
    }
    __syncthreads();
  }
  #pragma unroll
  for (int i=0;i<8;i++) {
    #pragma unroll
    for (int p=0;p<4;p++) {
      float lo, hi; unpack2f(acc[i][p], lo, hi);
      lo = lo>0.f?lo:0.f; hi = hi>0.f?hi:0.f;
      *reinterpret_cast<unsigned long long*>(&g_h2[g*16384 + (n0+i)*256 + o0+2*p]) = pack2f(lo,hi);
    }
  }
}

// ---------------- layer 3: h3 = relu(W3 @ h2 + b3), K=256, O=256 ----------------

__global__ void __launch_bounds__(256) layer3_kernel(const float* __restrict__ b3)
{
  __shared__ float s_in[64*32];
  __shared__ float s_w[32*256];
  int tx = threadIdx.x;
  int g = blockIdx.x;
  int ng = tx >> 5, og = tx & 31;
  int n0 = ng*8, o0 = og*8;
  unsigned long long acc[8][4];
  #pragma unroll
  for (int p=0;p<4;p++) {
    unsigned long long bb = pack2f(b3[o0+2*p], b3[o0+2*p+1]);
    #pragma unroll
    for (int i=0;i<8;i++) acc[i][p] = bb;
  }
  int kk_me = tx & 31;
  int nbase = tx >> 5;
  for (int kt=0; kt<8; kt++) {
    #pragma unroll
    for (int t=0;t<32;t++) s_w[tx + 256*t] = g_W3t[kt*8192 + tx + 256*t];
    #pragma unroll
    for (int t=0;t<8;t++) {
      int n = nbase + 8*t;
      s_in[n*32 + kk_me] = g_h2[g*16384 + n*256 + kt*32 + kk_me];
    }
    __syncthreads();
    #pragma unroll 8
    for (int kk=0; kk<32; kk++) {
      unsigned long long bf[4];
      const float* wr = s_w + kk*256 + o0;
      #pragma unroll
      for (int p=0;p<4;p++) bf[p] = *reinterpret_cast<const unsigned long long*>(wr + 2*p);
      #pragma unroll
      for (int i=0;i<8;i++) {
        unsigned long long aa = dup2f(s_in[(n0+i)*32 + kk]);
        #pragma unroll
        for (int p=0;p<4;p++) ffma2(acc[i][p], aa, bf[p]);
      }
    }
    __syncthreads();
  }
  #pragma unroll
  for (int i=0;i<8;i++) {
    #pragma unroll
    for (int p=0;p<4;p++) {
      float lo, hi; unpack2f(acc[i][p], lo, hi);
      lo = lo>0.f?lo:0.f; hi = hi>0.f?hi:0.f;
      *reinterpret_cast<unsigned long long*>(&g_h3[g*16384 + (n0+i)*256 + o0+2*p]) = pack2f(lo,hi);
    }
  }
}

// ---------------- layer 4 + heads: K=256, O=128, h4 stays in registers ----------------

__global__ void __launch_bounds__(256) layer4_heads_kernel(
  const float* __restrict__ b4,
  const float* __restrict__ stage1,
  const float* __restrict__ reg_w, const float* __restrict__ reg_b,
  const float* __restrict__ cls_w, const float* __restrict__ cls_b,
  const float* __restrict__ dc_reg_w, const float* __restrict__ dc_reg_b,
  const float* __restrict__ dc_cls_w, const float* __restrict__ dc_cls_b,
  float* __restrict__ out)
{
  __shared__ float s_in[64*32];
  __shared__ float s_w[32*256];   // also reused for head scratch (8192 floats)
  int tx = threadIdx.x;
  int g = blockIdx.x;
  int ng = tx >> 5, og = tx & 31;
  int n0 = ng*8, o0 = og*4;       // O=128: 4 o's per thread
  unsigned long long acc[8][2];
  #pragma unroll
  for (int p=0;p<2;p++) {
    unsigned long long bb = pack2f(b4[o0+2*p], b4[o0+2*p+1]);
    #pragma unroll
    for (int i=0;i<8;i++) acc[i][p] = bb;
  }
  int kk_me = tx & 31;
  int nbase = tx >> 5;
  for (int kt=0; kt<8; kt++) {
    // W4t tile [32][128] = 4096 floats
    #pragma unroll
    for (int t=0;t<16;t++) s_w[tx + 256*t] = g_W4t[kt*4096 + ((tx + 256*t) & 4095)];
    #pragma unroll
    for (int t=0;t<8;t++) {
      int n = nbase + 8*t;
      s_in[n*32 + kk_me] = g_h3[g*16384 + n*256 + kt*32 + kk_me];
    }
    __syncthreads();
    #pragma unroll 8
    for (int kk=0; kk<32; kk++) {
      unsigned long long bf[2];
      const float* wr = s_w + kk*128 + o0;
      #pragma unroll
      for (int p=0;p<2;p++) bf[p] = *reinterpret_cast<const unsigned long long*>(wr + 2*p);
      #pragma unroll
      for (int i=0;i<8;i++) {
        unsigned long long aa = dup2f(s_in[(n0+i)*32 + kk]);
        #pragma unroll
        for (int p=0;p<2;p++) ffma2(acc[i][p], aa, bf[p]);
      }
    }
    __syncthreads();
  }
  // relu into v[8][4]
  float v[8][4];
  #pragma unroll
  for (int i=0;i<8;i++) {
    #pragma unroll
    for (int p=0;p<2;p++) {
      float lo, hi; unpack2f(acc[i][p], lo, hi);
      v[i][2*p]   = lo>0.f?lo:0.f;
      v[i][2*p+1] = hi>0.f?hi:0.f;
    }
  }

  // head scratch in s_w: dc [0,640), rw2 [640,1920), partials [2048, 2048+2560)
  float* s_dc  = s_w;
  float* s_rw2 = s_w + 640;
  float* s_pt  = s_w + 2048;
  for (int i=tx;i<512;i+=256) s_dc[i]     = dc_reg_w[i];
  for (int i=tx;i<128;i+=256) s_dc[512+i] = dc_cls_w[i];
  for (int i=tx;i<1280;i+=256) {
    int c = i>>7, j = i&127;
    s_rw2[i] = (c<8) ? reg_w[c*384 + 256 + j] : cls_w[(c-8)*384 + 256 + j];
  }
  __syncthreads();

  // per-thread partial for each of 10 channels over its (n,j) microtile
  #pragma unroll
  for (int c=0;c<10;c++) {
    const float* dcw = (c<8) ? (s_dc + c*64) : (s_dc + 512 + (c-8)*64);
    const float* rw2 = s_rw2 + c*128 + o0;
    float pc_ = 0.f;
    #pragma unroll
    for (int i=0;i<8;i++) {
      float t = 0.f;
      #pragma unroll
      for (int q=0;q<4;q++) t = fmaf(rw2[q], v[i][q], t);
      pc_ = fmaf(dcw[n0+i], t, pc_);
    }
    s_pt[c*256 + tx] = pc_;
  }
  __syncthreads();

  // warp w reduces channels c = w, w+8
  int wid = tx >> 5, lane = tx & 31;
  for (int c = wid; c < 10; c += 8) {
    float hd = 0.f;
    #pragma unroll
    for (int t=0;t<8;t++) hd += s_pt[c*256 + lane + 32*t];
    // s1 dot: rw[c][0..255] . stage1[g]
    const float* rw = (c<8) ? (reg_w + c*384) : (cls_w + (c-8)*384);
    const float* s1 = stage1 + g*256;
    float s1d = 0.f;
    #pragma unroll
    for (int t=0;t<8;t++) {
      int j = lane + 32*t;
      s1d = fmaf(rw[j], s1[j], s1d);
    }
    // S = sum_n dc[c][n]
    const float* dcw = (c<8) ? (s_dc + c*64) : (s_dc + 512 + (c-8)*64);
    float S = dcw[lane] + dcw[lane+32];
    #pragma unroll
    for (int off=16; off>0; off>>=1) {
      hd  += __shfl_down_sync(0xffffffffu, hd,  off);
      s1d += __shfl_down_sync(0xffffffffu, s1d, off);
      S   += __shfl_down_sync(0xffffffffu, S,   off);
    }
    if (lane==0) {
      float bc  = (c<8) ? reg_b[c] : cls_b[c-8];
      float dcb = (c<8) ? dc_reg_b[c] : dc_cls_b[c-8];
      float o = hd + (s1d + bc)*S + dcb;
      if (c < 8) out[2048 + g*8 + c] = o;
      else       out[g*2 + (c-8)]   = o;
    }
  }
}

// ---------------- launch ----------------

extern "C" void kernel_launch(void* const* d_in, const int* in_sizes, int n_in,
                              void* d_out, int out_size) {
  const float* grasp  = (const float*)d_in[0];
  const float* pc     = (const float*)d_in[1];
  const float* stage1 = (const float*)d_in[3];
  const float* W1 = (const float*)d_in[4];  const float* b1 = (const float*)d_in[5];
  const float* W2 = (const float*)d_in[6];  const float* b2 = (const float*)d_in[7];
  const float* W3 = (const float*)d_in[8];  const float* b3 = (const float*)d_in[9];
  const float* W4 = (const float*)d_in[10]; const float* b4 = (const float*)d_in[11];
  const float* reg_w = (const float*)d_in[12]; const float* reg_b = (const float*)d_in[13];
  const float* cls_w = (const float*)d_in[14]; const float* cls_b = (const float*)d_in[15];
  const float* dcrw  = (const float*)d_in[16]; const float* dcrb  = (const float*)d_in[17];
  const float* dccw  = (const float*)d_in[18]; const float* dccb  = (const float*)d_in[19];
  float* out = (float*)d_out;

  prep_points<<<(BATCH*APTS + 255)/256, 256>>>(pc);
  prep_grasp<<<(BN + 255)/256, 256>>>(grasp);
  transpose_w<<<(512*256 + 256*256 + 256*128 + 255)/256, 256>>>(W2, W3, W4);
  bq_kernel<<<BN, 128>>>(grasp, out);
  layer12_kernel<<<BN, 256>>>(W1, b1, b2);
  layer3_kernel<<<BN, 256>>>(b3);
  layer4_heads_kernel<<<BN, 256>>>(b4, stage1, reg_w, reg_b, cls_w, cls_b,
                                   dcrw, dcrb, dccw, dccb, out);
}

// round 6
// speedup vs baseline: 2.6821x; 2.6821x over previous
#include <cuda_runtime.h>
#include <cuda_bf16.h>
#include <mma.h>
#include <cstdint>

using namespace nvcuda;

#define BATCH 2
#define APTS 20000
#define BN 1024
#define NNEI 192
#define GNUM 64

static __device__ float4 g_p4[BATCH*APTS];                 // x,y,z,|x|^2
static __device__ float  g_RtC[BN][12];
static __device__ int    g_gmask[BN];
static __device__ float  g_gpts[BN*GNUM*3];
static __device__ __nv_bfloat16 g_W2tb[512*256];           // k-major [k][o]
static __device__ __nv_bfloat16 g_W3tb[256*256];
static __device__ __nv_bfloat16 g_W4tb[256*128];
static __device__ float  g_h2[BN*64*256];                  // raw (pre-bias/relu) f32
static __device__ float  g_h3[BN*64*256];                  // raw f32

// ---------------- prep kernels ----------------

__global__ void prep_points(const float* __restrict__ pc) {
  int i = blockIdx.x*blockDim.x + threadIdx.x;
  if (i >= BATCH*APTS) return;
  float x = pc[i*6+0], y = pc[i*6+1], z = pc[i*6+2];
  float xx = __fadd_rn(__fadd_rn(__fmul_rn(x,x),__fmul_rn(y,y)),__fmul_rn(z,z));
  g_p4[i] = make_float4(x,y,z,xx);
}

__global__ void prep_grasp(const float* __restrict__ grasp) {
  int g = blockIdx.x*blockDim.x + threadIdx.x;
  if (g >= BN) return;
  const float* gr = grasp + g*8;
  float s8 = 0.f;
  for (int k=0;k<8;k++) s8 += gr[k];
  g_gmask[g] = (s8 != -8.0f) ? 1 : 0;
  float cx=gr[0], cy=gr[1], cz=gr[2];
  float ay0=gr[3], ay1=gr[4], ay2=gr[5];
  float ang=gr[6];
  float c=cosf(ang), s=sinf(ang);
  float ny = sqrtf(ay0*ay0+ay1*ay1+ay2*ay2);
  ay0 = ay0/(ny+1e-12f); ay1 = ay1/(ny+1e-12f); ay2 = ay2/(ny+1e-12f);
  float ax0=ay1, ax1=-ay0;
  float nx = sqrtf(ax0*ax0+ax1*ax1);
  ax0 = ax0/(nx+1e-12f); ax1 = ax1/(nx+1e-12f);
  float az0 = ax1*ay2;
  float az1 = -ax0*ay2;
  float az2 = ax0*ay1 - ax1*ay0;
  float nz = sqrtf(az0*az0+az1*az1+az2*az2);
  if (nz == 0.0f) { az0=0.f; az1=0.f; az2=1.f; }
  else { az0/=nz; az1/=nz; az2/=nz; }
  float ap0 = c*ax0 + s*az0;
  float ap1 = c*ax1 + s*az1;
  float ap2 = s*az2;
  float na = sqrtf(ap0*ap0+ap1*ap1+ap2*ap2);
  ap0 = ap0/(na+1e-12f); ap1 = ap1/(na+1e-12f); ap2 = ap2/(na+1e-12f);
  float mn0 = ap1*ay2 - ap2*ay1;
  float mn1 = ap2*ay0 - ap0*ay2;
  float mn2 = ap0*ay1 - ap1*ay0;
  float* R = g_RtC[g];
  R[0]=ap0; R[1]=ap1; R[2]=ap2;
  R[3]=ay0; R[4]=ay1; R[5]=ay2;
  R[6]=mn0; R[7]=mn1; R[8]=mn2;
  R[9]=cx;  R[10]=cy; R[11]=cz;
}

__global__ void transpose_w(const float* __restrict__ W2, const float* __restrict__ W3,
                            const float* __restrict__ W4) {
  int id = blockIdx.x*blockDim.x + threadIdx.x;
  if (id < 512*256) {
    int k = id >> 8, o = id & 255;
    g_W2tb[id] = __float2bfloat16(W2[o*512 + k]);
  } else if (id < 512*256 + 256*256) {
    int r = id - 512*256;
    int k = r >> 8, o = r & 255;
    g_W3tb[r] = __float2bfloat16(W3[o*256 + k]);
  } else if (id < 512*256 + 256*256 + 256*128) {
    int r = id - (512*256 + 256*256);
    int k = r >> 7, o = r & 127;
    g_W4tb[r] = __float2bfloat16(W4[o*256 + k]);
  }
}

// ---------------- ball query + gripper transform + selection ----------------
// 8 warps/block, each scans 2500 contiguous points with float4 loads.

__global__ void __launch_bounds__(256) bq_kernel(const float* __restrict__ grasp,
                                                 float* __restrict__ out) {
  __shared__ int s_list[8][NNEI];
  __shared__ int s_app[8], s_tot[8];
  __shared__ int s_nbr[NNEI];
  __shared__ float s_t[NNEI][3];
  __shared__ unsigned char s_in[NNEI];
  __shared__ int s_sel[GNUM];
  __shared__ int s_totvalid, s_ccount;
  __shared__ float s_R[12];

  int g = blockIdx.x;
  int b = g >> 9;
  int tx = threadIdx.x;
  int w = tx >> 5, lane = tx & 31;
  const float* gr = grasp + g*8;
  float cx=gr[0], cy=gr[1], cz=gr[2];
  float cc = __fadd_rn(__fadd_rn(__fmul_rn(cx,cx),__fmul_rn(cy,cy)),__fmul_rn(cz,cz));
  if (tx < 12) s_R[tx] = g_RtC[g][tx];

  const int chunk = APTS/8; // 2500
  int lo = b*APTS + w*chunk, hi = lo + chunk;
  int tot=0, app=0;
  for (int base=lo; base<hi; base+=32) {
    int i = base + lane;
    bool ok=false;
    if (i < hi) {
      float4 p = g_p4[i];
      float dot = __fadd_rn(__fadd_rn(__fmul_rn(cx,p.x),__fmul_rn(cy,p.y)),
                            __fmul_rn(cz,p.z));
      float d2 = __fsub_rn(__fadd_rn(cc, p.w), __fmul_rn(2.0f,dot));
      ok = d2 < 0.09f;
    }
    unsigned mb = __ballot_sync(0xffffffffu, ok);
    if (ok) {
      int pos = app + __popc(mb & ((1u<<lane)-1u));
      if (pos < NNEI) s_list[w][pos] = i - b*APTS;
    }
    tot += __popc(mb);
    app = tot < NNEI ? tot : NNEI;
  }
  if (lane==0) { s_app[w]=app; s_tot[w]=tot; }
  __syncthreads();

  if (tx==0) {
    int totv = 0;
    for (int ww=0; ww<8; ww++) totv += s_tot[ww];
    int run=0;
    for (int ww=0; ww<8 && run<NNEI; ww++) {
      int t = s_app[ww]; if (t > NNEI-run) t = NNEI-run;
      for (int j=0;j<t;j++) s_nbr[run+j] = s_list[ww][j];
      run += t;
    }
    int pad = (run>0) ? s_nbr[0] : 0;
    for (int j=run;j<NNEI;j++) s_nbr[j]=pad;
    s_totvalid = totv;
  }
  __syncthreads();

  for (int p=tx; p<NNEI; p+=blockDim.x) {
    float4 pt = g_p4[b*APTS + s_nbr[p]];
    float vx = pt.x-s_R[9], vy = pt.y-s_R[10], vz = pt.z-s_R[11];
    float t0 = s_R[0]*vx + s_R[1]*vy + s_R[2]*vz;
    float t1 = s_R[3]*vx + s_R[4]*vy + s_R[5]*vz;
    float t2 = s_R[6]*vx + s_R[7]*vy + s_R[8]*vz;
    s_t[p][0]=t0; s_t[p][1]=t1; s_t[p][2]=t2;
    bool ins = (t0>0.0f)&&(t0<0.3f)&&(t1>-0.15f)&&(t1<0.15f)&&(t2>-0.1f)&&(t2<0.1f);
    s_in[p] = ins ? 1 : 0;
  }
  __syncthreads();

  if (tx < 32) {
    int totI=0, first=-1;
    for (int ch=0; ch<NNEI/32; ch++) {
      int p = ch*32 + lane;
      bool ok = s_in[p]!=0;
      unsigned mm = __ballot_sync(0xffffffffu, ok);
      int app64 = totI<GNUM ? totI : GNUM;
      if (ok) {
        int pos = app64 + __popc(mm & ((1u<<lane)-1u));
        if (pos < GNUM) s_sel[pos] = p;
      }
      if (first<0 && mm) first = ch*32 + __ffs(mm)-1;
      totI += __popc(mm);
    }
    int cc64 = totI<GNUM ? totI : GNUM;
    int pad = (totI>0) ? first : 0;
    for (int j=lane; j<GNUM; j+=32) if (j>=cc64) s_sel[j]=pad;
    if (lane==0) s_ccount = cc64;
  }
  __syncthreads();

  for (int idx=tx; idx<GNUM*3; idx+=blockDim.x) {
    int n = idx/3, d = idx - n*3;
    g_gpts[g*(GNUM*3)+idx] = s_t[s_sel[n]][d];
  }
  if (tx==0) {
    bool mk = (s_totvalid>0) && (s_ccount>0) && (g_gmask[g]!=0);
    out[10240 + g] = mk ? 1.0f : 0.0f;
  }
}

// ---------------- layer 1+2 fused (wmma bf16): raw h2 = h1 @ W2t ----------------
// one block/grasp, 256 thr = 8 warps (4 m-tiles x 2 n-halves).
// h1 computed on the fly per 64-wide k-tile; h2 stored raw f32 (bias/relu fused into next stage).

#define APAD 72
#define BPAD 264

__global__ void __launch_bounds__(256) layer12_kernel(
  const float* __restrict__ W1, const float* __restrict__ b1)
{
  __shared__ __nv_bfloat16 s_a[64*APAD];
  __shared__ __nv_bfloat16 s_b[64*BPAD];
  __shared__ float s_pts[GNUM*3];
  int tx = threadIdx.x;
  int g = blockIdx.x;
  int wid = tx >> 5;
  if (tx < GNUM*3) s_pts[tx] = g_gpts[g*(GNUM*3)+tx];

  wmma::fragment<wmma::accumulator,16,16,16,float> acc[8];
  #pragma unroll
  for (int f=0;f<8;f++) wmma::fill_fragment(acc[f], 0.0f);
  int m0 = (wid & 3) * 16;
  int n0 = (wid >> 2) * 128;

  int kl = tx & 63;
  int nb = tx >> 6;
  __syncthreads();

  for (int kt=0; kt<8; kt++) {
    // stage B tile [64][256] bf16 (rows padded to 264)
    #pragma unroll
    for (int t=0;t<8;t++) {
      int idx = tx + 256*t;
      int r = idx >> 5, c8 = idx & 31;
      reinterpret_cast<uint4*>(s_b + r*BPAD)[c8] =
        reinterpret_cast<const uint4*>(g_W2tb + (kt*64 + r)*256)[c8];
    }
    // compute h1 tile [64][64] bf16
    int k = kt*64 + kl;
    float w0=W1[k*3], w1=W1[k*3+1], w2=W1[k*3+2], bb1=b1[k];
    #pragma unroll
    for (int t=0;t<16;t++) {
      int n = nb*16 + t;
      float v = fmaf(w2, s_pts[n*3+2], fmaf(w1, s_pts[n*3+1], fmaf(w0, s_pts[n*3+0], bb1)));
      s_a[n*APAD + kl] = __float2bfloat16(v>0.f ? v : 0.f);
    }
    __syncthreads();
    #pragma unroll
    for (int ks=0; ks<4; ks++) {
      wmma::fragment<wmma::matrix_a,16,16,16,__nv_bfloat16,wmma::row_major> fa;
      wmma::load_matrix_sync(fa, s_a + m0*APAD + ks*16, APAD);
      #pragma unroll
      for (int f=0;f<8;f++) {
        wmma::fragment<wmma::matrix_b,16,16,16,__nv_bfloat16,wmma::row_major> fb;
        wmma::load_matrix_sync(fb, s_b + (ks*16)*BPAD + n0 + 16*f, BPAD);
        wmma::mma_sync(acc[f], fa, fb, acc[f]);
      }
    }
    __syncthreads();
  }
  #pragma unroll
  for (int f=0;f<8;f++)
    wmma::store_matrix_sync(g_h2 + g*16384 + m0*256 + n0 + 16*f, acc[f], 256, wmma::mem_row_major);
}

// ---------------- layer 3 (wmma): raw h3 = relu(h2+b2) @ W3t ----------------

__global__ void __launch_bounds__(256) layer3_kernel(const float* __restrict__ b2)
{
  __shared__ __nv_bfloat16 s_a[64*APAD];
  __shared__ __nv_bfloat16 s_b[64*BPAD];
  int tx = threadIdx.x;
  int g = blockIdx.x;
  int wid = tx >> 5;
  wmma::fragment<wmma::accumulator,16,16,16,float> acc[8];
  #pragma unroll
  for (int f=0;f<8;f++) wmma::fill_fragment(acc[f], 0.0f);
  int m0 = (wid & 3) * 16;
  int n0 = (wid >> 2) * 128;
  int kl = tx & 63;
  int nb = tx >> 6;

  for (int kt=0; kt<4; kt++) {
    #pragma unroll
    for (int t=0;t<8;t++) {
      int idx = tx + 256*t;
      int r = idx >> 5, c8 = idx & 31;
      reinterpret_cast<uint4*>(s_b + r*BPAD)[c8] =
        reinterpret_cast<const uint4*>(g_W3tb + (kt*64 + r)*256)[c8];
    }
    int k = kt*64 + kl;
    float bb = b2[k];
    #pragma unroll
    for (int t=0;t<16;t++) {
      int n = nb*16 + t;
      float v = g_h2[g*16384 + n*256 + k] + bb;
      s_a[n*APAD + kl] = __float2bfloat16(v>0.f ? v : 0.f);
    }
    __syncthreads();
    #pragma unroll
    for (int ks=0; ks<4; ks++) {
      wmma::fragment<wmma::matrix_a,16,16,16,__nv_bfloat16,wmma::row_major> fa;
      wmma::load_matrix_sync(fa, s_a + m0*APAD + ks*16, APAD);
      #pragma unroll
      for (int f=0;f<8;f++) {
        wmma::fragment<wmma::matrix_b,16,16,16,__nv_bfloat16,wmma::row_major> fb;
        wmma::load_matrix_sync(fb, s_b + (ks*16)*BPAD + n0 + 16*f, BPAD);
        wmma::mma_sync(acc[f], fa, fb, acc[f]);
      }
    }
    __syncthreads();
  }
  #pragma unroll
  for (int f=0;f<8;f++)
    wmma::store_matrix_sync(g_h3 + g*16384 + m0*256 + n0 + 16*f, acc[f], 256, wmma::mem_row_major);
}

// ---------------- layer 4 + heads ----------------
// wmma K=256, N=128; acc -> smem f32; fused fp32 head contraction.

#define B4PAD 136
#define OPAD 132

__global__ void __launch_bounds__(256) layer4_heads_kernel(
  const float* __restrict__ b3, const float* __restrict__ b4,
  const float* __restrict__ stage1,
  const float* __restrict__ reg_w, const float* __restrict__ reg_b,
  const float* __restrict__ cls_w, const float* __restrict__ cls_b,
  const float* __restrict__ dc_reg_w, const float* __restrict__ dc_reg_b,
  const float* __restrict__ dc_cls_w, const float* __restrict__ dc_cls_b,
  float* __restrict__ out)
{
  // phase-aliased smem: staging (A+B bf16) then s_out f32
  __shared__ char s_mem[64*OPAD*4];            // 33792 B >= staging 26624 B
  __shared__ float s_hd[640 + 1280 + 80];      // dc, rw2, warp partials
  __nv_bfloat16* s_a = reinterpret_cast<__nv_bfloat16*>(s_mem);                 // 64*72
  __nv_bfloat16* s_b = reinterpret_cast<__nv_bfloat16*>(s_mem) + 64*APAD;       // 64*136
  float* s_out = reinterpret_cast<float*>(s_mem);                               // 64*132

  int tx = threadIdx.x;
  int g = blockIdx.x;
  int wid = tx >> 5, lane = tx & 31;
  wmma::fragment<wmma::accumulator,16,16,16,float> acc[4];
  #pragma unroll
  for (int f=0;f<4;f++) wmma::fill_fragment(acc[f], 0.0f);
  int m0 = (wid & 3) * 16;
  int n0 = (wid >> 2) * 64;
  int kl = tx & 63;
  int nb = tx >> 6;

  // head weights staging (separate region, safe during mma phase)
  float* s_dc  = s_hd;          // 640
  float* s_rw2 = s_hd + 640;    // 1280
  float* s_pt  = s_hd + 1920;   // 80
  for (int i=tx;i<512;i+=256) s_dc[i]     = dc_reg_w[i];
  for (int i=tx;i<128;i+=256) s_dc[512+i] = dc_cls_w[i];
  for (int i=tx;i<1280;i+=256) {
    int c = i>>7, j = i&127;
    s_rw2[i] = (c<8) ? reg_w[c*384 + 256 + j] : cls_w[(c-8)*384 + 256 + j];
  }

  for (int kt=0; kt<4; kt++) {
    #pragma unroll
    for (int t=0;t<4;t++) {
      int idx = tx + 256*t;
      int r = idx >> 4, c8 = idx & 15;
      reinterpret_cast<uint4*>(s_b + r*B4PAD)[c8] =
        reinterpret_cast<const uint4*>(g_W4tb + (kt*64 + r)*128)[c8];
    }
    int k = kt*64 + kl;
    float bb = b3[k];
    #pragma unroll
    for (int t=0;t<16;t++) {
      int n = nb*16 + t;
      float v = g_h3[g*16384 + n*256 + k] + bb;
      s_a[n*APAD + kl] = __float2bfloat16(v>0.f ? v : 0.f);
    }
    __syncthreads();
    #pragma unroll
    for (int ks=0; ks<4; ks++) {
      wmma::fragment<wmma::matrix_a,16,16,16,__nv_bfloat16,wmma::row_major> fa;
      wmma::load_matrix_sync(fa, s_a + m0*APAD + ks*16, APAD);
      #pragma unroll
      for (int f=0;f<4;f++) {
        wmma::fragment<wmma::matrix_b,16,16,16,__nv_bfloat16,wmma::row_major> fb;
        wmma::load_matrix_sync(fb, s_b + (ks*16)*B4PAD + n0 + 16*f, B4PAD);
        wmma::mma_sync(acc[f], fa, fb, acc[f]);
      }
    }
    __syncthreads();
  }
  #pragma unroll
  for (int f=0;f<4;f++)
    wmma::store_matrix_sync(s_out + m0*OPAD + n0 + 16*f, acc[f], OPAD, wmma::mem_row_major);
  __syncthreads();

  // heads: thread (n-group wid -> 8 rows, lane -> 4 cols)
  int hn0 = wid*8, j0 = lane*4;
  float bj[4];
  #pragma unroll
  for (int q=0;q<4;q++) bj[q] = b4[j0+q];
  #pragma unroll
  for (int c=0;c<10;c++) {
    const float* dcw = (c<8) ? (s_dc + c*64) : (s_dc + 512 + (c-8)*64);
    const float* rw2 = s_rw2 + c*128 + j0;
    float pc_ = 0.f;
    #pragma unroll
    for (int i=0;i<8;i++) {
      float t = 0.f;
      #pragma unroll
      for (int q=0;q<4;q++) {
        float h = s_out[(hn0+i)*OPAD + j0+q] + bj[q];
        h = h>0.f ? h : 0.f;
        t = fmaf(rw2[q], h, t);
      }
      pc_ = fmaf(dcw[hn0+i], t, pc_);
    }
    #pragma unroll
    for (int off=16; off>0; off>>=1) pc_ += __shfl_down_sync(0xffffffffu, pc_, off);
    if (lane==0) s_pt[c*8 + wid] = pc_;
  }
  __syncthreads();

  for (int c = wid; c < 10; c += 8) {
    float hd = (lane < 8) ? s_pt[c*8 + lane] : 0.f;
    const float* rw = (c<8) ? (reg_w + c*384) : (cls_w + (c-8)*384);
    const float* s1 = stage1 + g*256;
    float s1d = 0.f;
    #pragma unroll
    for (int t=0;t<8;t++) {
      int j = lane + 32*t;
      s1d = fmaf(rw[j], s1[j], s1d);
    }
    const float* dcw = (c<8) ? (s_dc + c*64) : (s_dc + 512 + (c-8)*64);
    float S = dcw[lane] + dcw[lane+32];
    #pragma unroll
    for (int off=16; off>0; off>>=1) {
      hd  += __shfl_down_sync(0xffffffffu, hd,  off);
      s1d += __shfl_down_sync(0xffffffffu, s1d, off);
      S   += __shfl_down_sync(0xffffffffu, S,   off);
    }
    if (lane==0) {
      float bc  = (c<8) ? reg_b[c] : cls_b[c-8];
      float dcb = (c<8) ? dc_reg_b[c] : dc_cls_b[c-8];
      float o = hd + (s1d + bc)*S + dcb;
      if (c < 8) out[2048 + g*8 + c] = o;
      else       out[g*2 + (c-8)]   = o;
    }
  }
}

// ---------------- launch ----------------

extern "C" void kernel_launch(void* const* d_in, const int* in_sizes, int n_in,
                              void* d_out, int out_size) {
  const float* grasp  = (const float*)d_in[0];
  const float* pc     = (const float*)d_in[1];
  const float* stage1 = (const float*)d_in[3];
  const float* W1 = (const float*)d_in[4];  const float* b1 = (const float*)d_in[5];
  const float* W2 = (const float*)d_in[6];  const float* b2 = (const float*)d_in[7];
  const float* W3 = (const float*)d_in[8];  const float* b3 = (const float*)d_in[9];
  const float* W4 = (const float*)d_in[10]; const float* b4 = (const float*)d_in[11];
  const float* reg_w = (const float*)d_in[12]; const float* reg_b = (const float*)d_in[13];
  const float* cls_w = (const float*)d_in[14]; const float* cls_b = (const float*)d_in[15];
  const float* dcrw  = (const float*)d_in[16]; const float* dcrb  = (const float*)d_in[17];
  const float* dccw  = (const float*)d_in[18]; const float* dccb  = (const float*)d_in[19];
  float* out = (float*)d_out;

  prep_points<<<(BATCH*APTS + 255)/256, 256>>>(pc);
  prep_grasp<<<(BN + 255)/256, 256>>>(grasp);
  transpose_w<<<(512*256 + 256*256 + 256*128 + 255)/256, 256>>>(W2, W3, W4);
  bq_kernel<<<BN, 256>>>(grasp, out);
  layer12_kernel<<<BN, 256>>>(W1, b1);
  layer3_kernel<<<BN, 256>>>(b2);
  layer4_heads_kernel<<<BN, 256>>>(b3, b4, stage1, reg_w, reg_b, cls_w, cls_b,
                                   dcrw, dcrb, dccw, dccb, out);
}